// round 12
// baseline (speedup 1.0000x reference)
#include <cuda_runtime.h>
#include <cuda_bf16.h>
#include <cstdint>

#define NB      8
#define SEQ     1024
#define HIDDEN  1024
#define NHEADS  16
#define DHEAD   64
#define MTOT    (NB*SEQ)        // 8192
#define SZTERM  1.024e-5f       // S * ZERO = 1024 * 1e-8

// ---------------- scratch (no allocations allowed) ----------------
__device__ float g_q[NB*NHEADS*SEQ*DHEAD];     // [b][h][s][d]
__device__ float g_k[NB*NHEADS*SEQ*DHEAD];
__device__ float g_v[NB*NHEADS*SEQ*DHEAD];
__device__ float g_ctx[NB*SEQ*HIDDEN];         // [b][s][h*64+d]
__device__ __nv_bfloat16 g_ah[MTOT*HIDDEN];    // A hi (bf16 split)
__device__ __nv_bfloat16 g_al[MTOT*HIDDEN];    // A lo
__device__ __nv_bfloat16 g_wh[HIDDEN*HIDDEN];  // W hi
__device__ __nv_bfloat16 g_wl[HIDDEN*HIDDEN];  // W lo

// ================= helpers =================
__device__ __forceinline__ uint32_t smem_u32(const void* p) {
    uint32_t a;
    asm("{ .reg .u64 t; cvta.to.shared.u64 t, %1; cvt.u32.u64 %0, t; }" : "=r"(a) : "l"(p));
    return a;
}
__device__ __forceinline__ void cp_async16(uint32_t dst, const void* src) {
    asm volatile("cp.async.cg.shared.global [%0], [%1], 16;" :: "r"(dst), "l"(src) : "memory");
}
#define CP_COMMIT()  asm volatile("cp.async.commit_group;" ::: "memory")
#define CP_WAIT(n)   asm volatile("cp.async.wait_group %0;" :: "n"(n) : "memory")

#define SWZ128(o) ((o) ^ (((o) >> 3) & 0x70))

#define LDMX4(r, a) \
    asm volatile("ldmatrix.sync.aligned.m8n8.x4.shared.b16 {%0,%1,%2,%3}, [%4];" \
        : "=r"((r)[0]), "=r"((r)[1]), "=r"((r)[2]), "=r"((r)[3]) : "r"(a))

#define MMA16816(c, a, b) \
    asm volatile("mma.sync.aligned.m16n8k16.row.col.f32.bf16.bf16.f32 " \
        "{%0,%1,%2,%3}, {%4,%5,%6,%7}, {%8,%9}, {%0,%1,%2,%3};" \
        : "+f"((c)[0]), "+f"((c)[1]), "+f"((c)[2]), "+f"((c)[3]) \
        : "r"((a)[0]), "r"((a)[1]), "r"((a)[2]), "r"((a)[3]), "r"((b)[0]), "r"((b)[1]))

// ================= fp32 -> bf16 hi/lo split =================
__global__ __launch_bounds__(256)
void split_bf16(const float* __restrict__ x, __nv_bfloat16* __restrict__ hi,
                __nv_bfloat16* __restrict__ lo, int n4)
{
    int i = blockIdx.x * blockDim.x + threadIdx.x;
    if (i >= n4) return;
    float4 v = ((const float4*)x)[i];
    float f[4] = {v.x, v.y, v.z, v.w};
    __nv_bfloat16 h[4], l[4];
#pragma unroll
    for (int j = 0; j < 4; j++) {
        h[j] = __float2bfloat16_rn(f[j]);
        l[j] = __float2bfloat16_rn(f[j] - __bfloat162float(h[j]));
    }
    __nv_bfloat162* H = (__nv_bfloat162*)hi;
    __nv_bfloat162* L = (__nv_bfloat162*)lo;
    H[2*i]   = __halves2bfloat162(h[0], h[1]);
    H[2*i+1] = __halves2bfloat162(h[2], h[3]);
    L[2*i]   = __halves2bfloat162(l[0], l[1]);
    L[2*i+1] = __halves2bfloat162(l[2], l[3]);
}

// ================= mma.sync GEMM: C = A[M,K] @ W[N,K]^T + bias =================
// CTA 128x128, 8 warps (warp tile 64x32), K chunks of 64, 3-stage cp.async.
// Per k16: hi*hi + hi*lo + lo*hi  (2-term bf16 split of fp32)
#define TILE_BYTES 16384u                // 128 rows x 128B (64 bf16)
#define STAGE_BYTES (4u*TILE_BYTES)      // Ah, Al, Bh, Bl
#define TC_SMEM (3u*STAGE_BYTES)         // 196608

__device__ __forceinline__ void load_chunk(
    const __nv_bfloat16* __restrict__ Ah, const __nv_bfloat16* __restrict__ Al,
    const __nv_bfloat16* __restrict__ Bh, const __nv_bfloat16* __restrict__ Bl,
    int m0, int n0, int kc, uint32_t buf, int tid)
{
#pragma unroll
    for (int it = 0; it < 4; it++) {
        const int idx = tid + it*256;        // 0..1023
        const int row = idx >> 3;            // 0..127
        const int c   = idx & 7;             // 16B unit within row
        const uint32_t off = SWZ128((uint32_t)(row*128 + c*16));
        const size_t arow = (size_t)(m0 + row) * HIDDEN + kc*64 + c*8;
        const size_t brow = (size_t)(n0 + row) * HIDDEN + kc*64 + c*8;
        cp_async16(buf + 0*TILE_BYTES + off, Ah + arow);
        cp_async16(buf + 1*TILE_BYTES + off, Al + arow);
        cp_async16(buf + 2*TILE_BYTES + off, Bh + brow);
        cp_async16(buf + 3*TILE_BYTES + off, Bl + brow);
    }
    CP_COMMIT();
}

__global__ __launch_bounds__(256, 1)
void tcgemm(const __nv_bfloat16* __restrict__ Ah, const __nv_bfloat16* __restrict__ Al,
            const __nv_bfloat16* __restrict__ Bh, const __nv_bfloat16* __restrict__ Bl,
            const float* __restrict__ bias, float* __restrict__ C, int head_layout)
{
    extern __shared__ char smem[];
    const uint32_t sb = smem_u32(smem);
    const int tid  = threadIdx.x;
    const int lane = tid & 31;
    const int wid  = tid >> 5;
    const int m0 = blockIdx.y * 128;
    const int n0 = blockIdx.x * 128;
    const int wm = (wid & 1) * 64;     // warp m offset
    const int wn = (wid >> 1) * 32;    // warp n offset

    // ldmatrix lane addressing (bytes within tile)
    const int a_row   = wm + (lane & 15);
    const int a_kh    = (lane >> 4) * 16;               // k-half byte offset
    const int b_rr    = (lane & 7) + ((lane >> 4) << 3);  // row within 16-n group
    const int b_kh    = (lane & 8) ? 16 : 0;

    float acc[4][4][4];
#pragma unroll
    for (int mt = 0; mt < 4; mt++)
#pragma unroll
        for (int nt = 0; nt < 4; nt++)
#pragma unroll
            for (int j = 0; j < 4; j++) acc[mt][nt][j] = 0.0f;

    // prologue: chunks 0,1,2
#pragma unroll
    for (int s = 0; s < 3; s++)
        load_chunk(Ah, Al, Bh, Bl, m0, n0, s, sb + s*STAGE_BYTES, tid);

    for (int i = 0; i < 16; i++) {
        if (i < 14)       CP_WAIT(2);
        else if (i == 14) CP_WAIT(1);
        else              CP_WAIT(0);
        __syncthreads();

        const uint32_t buf = sb + (uint32_t)(i % 3) * STAGE_BYTES;
        const uint32_t bAh = buf;
        const uint32_t bAl = buf + 1*TILE_BYTES;
        const uint32_t bBh = buf + 2*TILE_BYTES;
        const uint32_t bBl = buf + 3*TILE_BYTES;

#pragma unroll
        for (int ks = 0; ks < 4; ks++) {
            const int kb = ks * 32;
            uint32_t aH[4][4], aL[4][4], bH[4][2], bL[4][2];
#pragma unroll
            for (int mt = 0; mt < 4; mt++) {
                const uint32_t ao = SWZ128((uint32_t)((a_row + mt*16)*128 + kb + a_kh));
                LDMX4(aH[mt], bAh + ao);
                LDMX4(aL[mt], bAl + ao);
            }
#pragma unroll
            for (int p = 0; p < 2; p++) {
                const uint32_t bo = SWZ128((uint32_t)((wn + p*16 + b_rr)*128 + kb + b_kh));
                uint32_t rh[4], rl[4];
                LDMX4(rh, bBh + bo);
                LDMX4(rl, bBl + bo);
                bH[2*p][0] = rh[0]; bH[2*p][1] = rh[1];
                bH[2*p+1][0] = rh[2]; bH[2*p+1][1] = rh[3];
                bL[2*p][0] = rl[0]; bL[2*p][1] = rl[1];
                bL[2*p+1][0] = rl[2]; bL[2*p+1][1] = rl[3];
            }
#pragma unroll
            for (int mt = 0; mt < 4; mt++)
#pragma unroll
                for (int nt = 0; nt < 4; nt++) {
                    MMA16816(acc[mt][nt], aH[mt], bH[nt]);
                    MMA16816(acc[mt][nt], aH[mt], bL[nt]);
                    MMA16816(acc[mt][nt], aL[mt], bH[nt]);
                }
        }
        __syncthreads();
        if (i + 3 < 16)
            load_chunk(Ah, Al, Bh, Bl, m0, n0, i + 3, buf, tid);
    }

    // epilogue
#pragma unroll
    for (int mt = 0; mt < 4; mt++) {
        const int r0 = wm + mt*16 + (lane >> 2);
#pragma unroll
        for (int half = 0; half < 2; half++) {
            const int m  = m0 + r0 + half*8;
            const int bb = m >> 10;
            const int ss = m & 1023;
#pragma unroll
            for (int nt = 0; nt < 4; nt++) {
                const int n = n0 + wn + nt*8 + 2*(lane & 3);
                float2 v;
                v.x = acc[mt][nt][half*2+0] + bias[n];
                v.y = acc[mt][nt][half*2+1] + bias[n+1];
                float* dst;
                if (head_layout) {
                    const int h = n >> 6;
                    const int d = n & 63;
                    dst = C + (((size_t)(bb*NHEADS + h))*SEQ + ss)*DHEAD + d;
                } else {
                    dst = C + (size_t)m * HIDDEN + n;
                }
                *(float2*)dst = v;
            }
        }
    }
}

// ---------------- flash attention with exact mask renormalization ----------------
#define FPAD 68
#define FTILE (64*FPAD)
#define FLASH_SMEM ((4*FTILE + 64) * sizeof(float))

__global__ __launch_bounds__(256)
void flash_attn(const float* __restrict__ Qh, const float* __restrict__ Kh,
                const float* __restrict__ Vh, const float* __restrict__ Qmask,
                const float* __restrict__ Kmask, float* __restrict__ ctx)
{
    extern __shared__ float sm[];
    float* Qs  = sm;
    float* Ks  = sm + FTILE;
    float* Vs  = sm + 2*FTILE;
    float* Ps  = sm + 3*FTILE;
    float* Kms = sm + 4*FTILE;

    const int tid = threadIdx.x;
    const int q0  = blockIdx.x * 64;
    const int h   = blockIdx.y;
    const int b   = blockIdx.z;
    const int bh  = b*NHEADS + h;
    const int ty  = tid >> 4;
    const int tx  = tid & 15;

    const float* Qbase = Qh + ((size_t)bh*SEQ + q0) * DHEAD;

#pragma unroll
    for (int it = 0; it < 4; it++) {
        int f  = tid + it*256;
        int r  = f >> 4;
        int c4 = (f & 15) * 4;
        float4 v = *(const float4*)(Qbase + (size_t)r*DHEAD + c4);
        Qs[(c4+0)*FPAD + r] = v.x;
        Qs[(c4+1)*FPAD + r] = v.y;
        Qs[(c4+2)*FPAD + r] = v.z;
        Qs[(c4+3)*FPAD + r] = v.w;
    }

    float m_[4], l_[4], lm_[4], o[4][4];
#pragma unroll
    for (int i = 0; i < 4; i++) {
        m_[i] = -1e30f; l_[i] = 0.0f; lm_[i] = 0.0f;
#pragma unroll
        for (int j = 0; j < 4; j++) o[i][j] = 0.0f;
    }

    for (int kt = 0; kt < SEQ; kt += 64) {
        __syncthreads();

        const float* Kbase = Kh + ((size_t)bh*SEQ + kt) * DHEAD;
        const float* Vbase = Vh + ((size_t)bh*SEQ + kt) * DHEAD;
#pragma unroll
        for (int it = 0; it < 4; it++) {
            int f  = tid + it*256;
            int r  = f >> 4;
            int c4 = (f & 15) * 4;
            float4 kv = *(const float4*)(Kbase + (size_t)r*DHEAD + c4);
            Ks[(c4+0)*FPAD + r] = kv.x;
            Ks[(c4+1)*FPAD + r] = kv.y;
            Ks[(c4+2)*FPAD + r] = kv.z;
            Ks[(c4+3)*FPAD + r] = kv.w;
            float4 vv = *(const float4*)(Vbase + (size_t)r*DHEAD + c4);
            *(float4*)&Vs[r*FPAD + c4] = vv;
        }
        if (tid < 64) Kms[tid] = Kmask[(size_t)b*SEQ + kt + tid];
        __syncthreads();

        float s_[4][4];
#pragma unroll
        for (int i = 0; i < 4; i++)
#pragma unroll
            for (int j = 0; j < 4; j++) s_[i][j] = 0.0f;

        for (int d = 0; d < DHEAD; d++) {
            float4 qa = *(const float4*)&Qs[d*FPAD + ty*4];
            float4 kb = *(const float4*)&Ks[d*FPAD + tx*4];
            float aq[4] = {qa.x, qa.y, qa.z, qa.w};
            float bk[4] = {kb.x, kb.y, kb.z, kb.w};
#pragma unroll
            for (int i = 0; i < 4; i++)
#pragma unroll
                for (int j = 0; j < 4; j++)
                    s_[i][j] += aq[i] * bk[j];
        }

        float kmv[4];
#pragma unroll
        for (int j = 0; j < 4; j++) kmv[j] = Kms[tx*4 + j];

#pragma unroll
        for (int i = 0; i < 4; i++) {
            float rmax = -1e30f;
#pragma unroll
            for (int j = 0; j < 4; j++) {
                s_[i][j] *= 8.0f;
                rmax = fmaxf(rmax, s_[i][j]);
            }
#pragma unroll
            for (int off = 8; off > 0; off >>= 1)
                rmax = fmaxf(rmax, __shfl_xor_sync(0xffffffffu, rmax, off));

            float mnew = fmaxf(m_[i], rmax);
            float fac  = __expf(m_[i] - mnew);
            float suml = 0.0f, sumlm = 0.0f;
#pragma unroll
            for (int j = 0; j < 4; j++) {
                float e = __expf(s_[i][j] - mnew);
                float p = e * kmv[j];
                s_[i][j] = p;
                suml  += e;
                sumlm += p;
            }
#pragma unroll
            for (int off = 8; off > 0; off >>= 1) {
                suml  += __shfl_xor_sync(0xffffffffu, suml,  off);
                sumlm += __shfl_xor_sync(0xffffffffu, sumlm, off);
            }
            l_[i]  = l_[i]*fac + suml;
            lm_[i] = lm_[i]*fac + sumlm;
            m_[i]  = mnew;
#pragma unroll
            for (int j = 0; j < 4; j++) o[i][j] *= fac;

            *(float4*)&Ps[(ty*4 + i)*FPAD + tx*4] =
                make_float4(s_[i][0], s_[i][1], s_[i][2], s_[i][3]);
        }
        __syncthreads();

        for (int k = 0; k < 64; k++) {
            float4 vv = *(const float4*)&Vs[k*FPAD + tx*4];
            float p0 = Ps[(ty*4+0)*FPAD + k];
            float p1 = Ps[(ty*4+1)*FPAD + k];
            float p2 = Ps[(ty*4+2)*FPAD + k];
            float p3 = Ps[(ty*4+3)*FPAD + k];
            o[0][0] += p0*vv.x; o[0][1] += p0*vv.y; o[0][2] += p0*vv.z; o[0][3] += p0*vv.w;
            o[1][0] += p1*vv.x; o[1][1] += p1*vv.y; o[1][2] += p1*vv.z; o[1][3] += p1*vv.w;
            o[2][0] += p2*vv.x; o[2][1] += p2*vv.y; o[2][2] += p2*vv.z; o[2][3] += p2*vv.w;
            o[3][0] += p3*vv.x; o[3][1] += p3*vv.y; o[3][2] += p3*vv.z; o[3][3] += p3*vv.w;
        }
    }

#pragma unroll
    for (int i = 0; i < 4; i++) {
        const int q = q0 + ty*4 + i;
        const float qm  = Qmask[(size_t)b*SEQ + q];
        const float inv = qm / (lm_[i] + l_[i]*SZTERM);
        float4 res = make_float4(o[i][0]*inv, o[i][1]*inv, o[i][2]*inv, o[i][3]*inv);
        *(float4*)&g_ctx[((size_t)b*SEQ + q)*HIDDEN + h*DHEAD + tx*4] = res;
    }
    (void)ctx;
}

// ---------------- launch ----------------
extern "C" void kernel_launch(void* const* d_in, const int* in_sizes, int n_in,
                              void* d_out, int out_size)
{
    const float* Q   = (const float*)d_in[0];
    const float* K   = (const float*)d_in[1];
    const float* V   = (const float*)d_in[2];
    const float* Qm  = (const float*)d_in[3];
    const float* Km  = (const float*)d_in[4];
    const float* Wq  = (const float*)d_in[5];
    const float* bq  = (const float*)d_in[6];
    const float* Wk  = (const float*)d_in[7];
    const float* bk  = (const float*)d_in[8];
    const float* Wv  = (const float*)d_in[9];
    const float* bv  = (const float*)d_in[10];
    const float* Wo  = (const float*)d_in[11];
    const float* bo  = (const float*)d_in[12];
    float* out = (float*)d_out;

    float *gq, *gk, *gv, *gctx;
    __nv_bfloat16 *ah, *al, *wh, *wl;
    cudaGetSymbolAddress((void**)&gq,   g_q);
    cudaGetSymbolAddress((void**)&gk,   g_k);
    cudaGetSymbolAddress((void**)&gv,   g_v);
    cudaGetSymbolAddress((void**)&gctx, g_ctx);
    cudaGetSymbolAddress((void**)&ah,   g_ah);
    cudaGetSymbolAddress((void**)&al,   g_al);
    cudaGetSymbolAddress((void**)&wh,   g_wh);
    cudaGetSymbolAddress((void**)&wl,   g_wl);

    cudaFuncSetAttribute(tcgemm, cudaFuncAttributeMaxDynamicSharedMemorySize, (int)TC_SMEM);
    cudaFuncSetAttribute(flash_attn, cudaFuncAttributeMaxDynamicSharedMemorySize,
                         (int)FLASH_SMEM);

    const int nA4 = MTOT*HIDDEN/4;       // 2097152
    const int nW4 = HIDDEN*HIDDEN/4;     // 262144
    dim3 ggrd(HIDDEN/128, MTOT/128);     // 8 x 64

    // Q projection
    split_bf16<<<nA4/256, 256>>>(Q, ah, al, nA4);
    split_bf16<<<nW4/256, 256>>>(Wq, wh, wl, nW4);
    tcgemm<<<ggrd, 256, TC_SMEM>>>(ah, al, wh, wl, bq, gq, 1);
    // K projection
    split_bf16<<<nA4/256, 256>>>(K, ah, al, nA4);
    split_bf16<<<nW4/256, 256>>>(Wk, wh, wl, nW4);
    tcgemm<<<ggrd, 256, TC_SMEM>>>(ah, al, wh, wl, bk, gk, 1);
    // V projection
    split_bf16<<<nA4/256, 256>>>(V, ah, al, nA4);
    split_bf16<<<nW4/256, 256>>>(Wv, wh, wl, nW4);
    tcgemm<<<ggrd, 256, TC_SMEM>>>(ah, al, wh, wl, bv, gv, 1);

    // attention
    dim3 fgrd(SEQ/64, NHEADS, NB);
    flash_attn<<<fgrd, 256, FLASH_SMEM>>>(gq, gk, gv, Qm, Km, gctx);

    // output projection
    split_bf16<<<nA4/256, 256>>>(gctx, ah, al, nA4);
    split_bf16<<<nW4/256, 256>>>(Wo, wh, wl, nW4);
    tcgemm<<<ggrd, 256, TC_SMEM>>>(ah, al, wh, wl, bo, out, 0);

    (void)in_sizes; (void)n_in; (void)out_size;
}

// round 13
// speedup vs baseline: 1.7145x; 1.7145x over previous
#include <cuda_runtime.h>
#include <cuda_bf16.h>
#include <cstdint>

#define NB      8
#define SEQ     1024
#define HIDDEN  1024
#define NHEADS  16
#define DHEAD   64
#define MTOT    (NB*SEQ)        // 8192
#define SZTERM  1.024e-5f       // S * ZERO = 1024 * 1e-8

// ---------------- scratch (no allocations allowed) ----------------
__device__ float g_ctx[NB*SEQ*HIDDEN];             // [b][s][h*64+d]
__device__ __nv_bfloat16 g_ah[MTOT*HIDDEN];        // GEMM A hi
__device__ __nv_bfloat16 g_al[MTOT*HIDDEN];        // GEMM A lo
__device__ __nv_bfloat16 g_wh[HIDDEN*HIDDEN];      // W hi
__device__ __nv_bfloat16 g_wl[HIDDEN*HIDDEN];      // W lo
__device__ __nv_bfloat16 g_qh[NB*NHEADS*SEQ*DHEAD];  // [b][h][s][d] splits
__device__ __nv_bfloat16 g_ql[NB*NHEADS*SEQ*DHEAD];
__device__ __nv_bfloat16 g_kh[NB*NHEADS*SEQ*DHEAD];
__device__ __nv_bfloat16 g_kl[NB*NHEADS*SEQ*DHEAD];
__device__ __nv_bfloat16 g_vh[NB*NHEADS*SEQ*DHEAD];
__device__ __nv_bfloat16 g_vl[NB*NHEADS*SEQ*DHEAD];

// ================= helpers =================
__device__ __forceinline__ uint32_t smem_u32(const void* p) {
    uint32_t a;
    asm("{ .reg .u64 t; cvta.to.shared.u64 t, %1; cvt.u32.u64 %0, t; }" : "=r"(a) : "l"(p));
    return a;
}
__device__ __forceinline__ void cp_async16(uint32_t dst, const void* src) {
    asm volatile("cp.async.cg.shared.global [%0], [%1], 16;" :: "r"(dst), "l"(src) : "memory");
}
#define CP_COMMIT()  asm volatile("cp.async.commit_group;" ::: "memory")
#define CP_WAIT(n)   asm volatile("cp.async.wait_group %0;" :: "n"(n) : "memory")

#define SWZ128(o) ((o) ^ (((o) >> 3) & 0x70))

#define LDMX4(r, a) \
    asm volatile("ldmatrix.sync.aligned.m8n8.x4.shared.b16 {%0,%1,%2,%3}, [%4];" \
        : "=r"((r)[0]), "=r"((r)[1]), "=r"((r)[2]), "=r"((r)[3]) : "r"(a))

#define LDMX4T(r, a) \
    asm volatile("ldmatrix.sync.aligned.m8n8.x4.trans.shared.b16 {%0,%1,%2,%3}, [%4];" \
        : "=r"((r)[0]), "=r"((r)[1]), "=r"((r)[2]), "=r"((r)[3]) : "r"(a))

#define MMA16816(c, a, b) \
    asm volatile("mma.sync.aligned.m16n8k16.row.col.f32.bf16.bf16.f32 " \
        "{%0,%1,%2,%3}, {%4,%5,%6,%7}, {%8,%9}, {%0,%1,%2,%3};" \
        : "+f"((c)[0]), "+f"((c)[1]), "+f"((c)[2]), "+f"((c)[3]) \
        : "r"((a)[0]), "r"((a)[1]), "r"((a)[2]), "r"((a)[3]), "r"((b)[0]), "r"((b)[1]))

__device__ __forceinline__ uint32_t pack_bf2(__nv_bfloat16 x, __nv_bfloat16 y) {
    __nv_bfloat162 t = __halves2bfloat162(x, y);
    return *(uint32_t*)&t;
}
__device__ __forceinline__ void split_pair(float x, float y, uint32_t& hi, uint32_t& lo) {
    __nv_bfloat16 hx = __float2bfloat16_rn(x);
    __nv_bfloat16 hy = __float2bfloat16_rn(y);
    hi = pack_bf2(hx, hy);
    lo = pack_bf2(__float2bfloat16_rn(x - __bfloat162float(hx)),
                  __float2bfloat16_rn(y - __bfloat162float(hy)));
}

// ================= fp32 -> bf16 hi/lo split =================
__global__ __launch_bounds__(256)
void split_bf16(const float* __restrict__ x, __nv_bfloat16* __restrict__ hi,
                __nv_bfloat16* __restrict__ lo, int n4)
{
    int i = blockIdx.x * blockDim.x + threadIdx.x;
    if (i >= n4) return;
    float4 v = ((const float4*)x)[i];
    float f[4] = {v.x, v.y, v.z, v.w};
    __nv_bfloat16 h[4], l[4];
#pragma unroll
    for (int j = 0; j < 4; j++) {
        h[j] = __float2bfloat16_rn(f[j]);
        l[j] = __float2bfloat16_rn(f[j] - __bfloat162float(h[j]));
    }
    __nv_bfloat162* H = (__nv_bfloat162*)hi;
    __nv_bfloat162* L = (__nv_bfloat162*)lo;
    H[2*i]   = __halves2bfloat162(h[0], h[1]);
    H[2*i+1] = __halves2bfloat162(h[2], h[3]);
    L[2*i]   = __halves2bfloat162(l[0], l[1]);
    L[2*i+1] = __halves2bfloat162(l[2], l[3]);
}

// ================= mma.sync GEMM: C = A[M,K] @ W[N,K]^T + bias =================
// mode 0: fp32 output [m][n];  mode 1: bf16 hi/lo split output in [b][h][s][d]
#define TILE_BYTES 16384u
#define STAGE_BYTES (4u*TILE_BYTES)
#define TC_SMEM (3u*STAGE_BYTES)         // 196608

__device__ __forceinline__ void load_chunk(
    const __nv_bfloat16* __restrict__ Ah, const __nv_bfloat16* __restrict__ Al,
    const __nv_bfloat16* __restrict__ Bh, const __nv_bfloat16* __restrict__ Bl,
    int m0, int n0, int kc, uint32_t buf, int tid)
{
#pragma unroll
    for (int it = 0; it < 4; it++) {
        const int idx = tid + it*256;
        const int row = idx >> 3;
        const int c   = idx & 7;
        const uint32_t off = SWZ128((uint32_t)(row*128 + c*16));
        const size_t arow = (size_t)(m0 + row) * HIDDEN + kc*64 + c*8;
        const size_t brow = (size_t)(n0 + row) * HIDDEN + kc*64 + c*8;
        cp_async16(buf + 0*TILE_BYTES + off, Ah + arow);
        cp_async16(buf + 1*TILE_BYTES + off, Al + arow);
        cp_async16(buf + 2*TILE_BYTES + off, Bh + brow);
        cp_async16(buf + 3*TILE_BYTES + off, Bl + brow);
    }
    CP_COMMIT();
}

__global__ __launch_bounds__(256, 1)
void tcgemm(const __nv_bfloat16* __restrict__ Ah, const __nv_bfloat16* __restrict__ Al,
            const __nv_bfloat16* __restrict__ Bh, const __nv_bfloat16* __restrict__ Bl,
            const float* __restrict__ bias, float* __restrict__ Cf,
            __nv_bfloat16* __restrict__ Ch, __nv_bfloat16* __restrict__ Cl, int mode)
{
    extern __shared__ char smem[];
    const uint32_t sb = smem_u32(smem);
    const int tid  = threadIdx.x;
    const int lane = tid & 31;
    const int wid  = tid >> 5;
    const int m0 = blockIdx.y * 128;
    const int n0 = blockIdx.x * 128;
    const int wm = (wid & 1) * 64;
    const int wn = (wid >> 1) * 32;

    const int a_row = wm + (lane & 15);
    const int a_kh  = (lane >> 4) * 16;
    const int b_rr  = (lane & 7) + ((lane >> 4) << 3);
    const int b_kh  = (lane & 8) ? 16 : 0;

    float acc[4][4][4];
#pragma unroll
    for (int mt = 0; mt < 4; mt++)
#pragma unroll
        for (int nt = 0; nt < 4; nt++)
#pragma unroll
            for (int j = 0; j < 4; j++) acc[mt][nt][j] = 0.0f;

#pragma unroll
    for (int s = 0; s < 3; s++)
        load_chunk(Ah, Al, Bh, Bl, m0, n0, s, sb + s*STAGE_BYTES, tid);

    for (int i = 0; i < 16; i++) {
        if (i < 14)       CP_WAIT(2);
        else if (i == 14) CP_WAIT(1);
        else              CP_WAIT(0);
        __syncthreads();

        const uint32_t buf = sb + (uint32_t)(i % 3) * STAGE_BYTES;
        const uint32_t bAh = buf;
        const uint32_t bAl = buf + 1*TILE_BYTES;
        const uint32_t bBh = buf + 2*TILE_BYTES;
        const uint32_t bBl = buf + 3*TILE_BYTES;

#pragma unroll
        for (int ks = 0; ks < 4; ks++) {
            const int kb = ks * 32;
            uint32_t aH[4][4], aL[4][4], bH[4][2], bL[4][2];
#pragma unroll
            for (int mt = 0; mt < 4; mt++) {
                const uint32_t ao = SWZ128((uint32_t)((a_row + mt*16)*128 + kb + a_kh));
                LDMX4(aH[mt], bAh + ao);
                LDMX4(aL[mt], bAl + ao);
            }
#pragma unroll
            for (int p = 0; p < 2; p++) {
                const uint32_t bo = SWZ128((uint32_t)((wn + p*16 + b_rr)*128 + kb + b_kh));
                uint32_t rh[4], rl[4];
                LDMX4(rh, bBh + bo);
                LDMX4(rl, bBl + bo);
                bH[2*p][0] = rh[0]; bH[2*p][1] = rh[1];
                bH[2*p+1][0] = rh[2]; bH[2*p+1][1] = rh[3];
                bL[2*p][0] = rl[0]; bL[2*p][1] = rl[1];
                bL[2*p+1][0] = rl[2]; bL[2*p+1][1] = rl[3];
            }
#pragma unroll
            for (int mt = 0; mt < 4; mt++)
#pragma unroll
                for (int nt = 0; nt < 4; nt++) {
                    MMA16816(acc[mt][nt], aH[mt], bH[nt]);
                    MMA16816(acc[mt][nt], aH[mt], bL[nt]);
                    MMA16816(acc[mt][nt], aL[mt], bH[nt]);
                }
        }
        __syncthreads();
        if (i + 3 < 16)
            load_chunk(Ah, Al, Bh, Bl, m0, n0, i + 3, buf, tid);
    }

#pragma unroll
    for (int mt = 0; mt < 4; mt++) {
        const int r0 = wm + mt*16 + (lane >> 2);
#pragma unroll
        for (int half = 0; half < 2; half++) {
            const int m  = m0 + r0 + half*8;
            const int bb = m >> 10;
            const int ss = m & 1023;
#pragma unroll
            for (int nt = 0; nt < 4; nt++) {
                const int n = n0 + wn + nt*8 + 2*(lane & 3);
                float v0 = acc[mt][nt][half*2+0] + bias[n];
                float v1 = acc[mt][nt][half*2+1] + bias[n+1];
                if (mode == 1) {
                    const int hh = n >> 6;
                    const int d  = n & 63;
                    const size_t idx = (((size_t)(bb*NHEADS + hh))*SEQ + ss)*DHEAD + d;
                    __nv_bfloat16 h0 = __float2bfloat16_rn(v0);
                    __nv_bfloat16 h1 = __float2bfloat16_rn(v1);
                    *(__nv_bfloat162*)(Ch + idx) = __halves2bfloat162(h0, h1);
                    *(__nv_bfloat162*)(Cl + idx) = __halves2bfloat162(
                        __float2bfloat16_rn(v0 - __bfloat162float(h0)),
                        __float2bfloat16_rn(v1 - __bfloat162float(h1)));
                } else {
                    *(float2*)(Cf + (size_t)m * HIDDEN + n) = make_float2(v0, v1);
                }
            }
        }
    }
}

// ================= tensor-core flash attention =================
// CTA: 128 q rows x one (b,h). 8 warps, warp = 16 q rows x 128 keys.
// smem: Qh/Ql tiles (32KB) + 2 stages of {Kh,Kl,Vh,Vl,Kms} (66048 B each)
#define AT_STAGE 66048u
#define AT_SMEM  (32768u + 2u*AT_STAGE)   // 164864

__device__ __forceinline__ void load_kv(
    uint32_t st, const __nv_bfloat16* __restrict__ Kh_, const __nv_bfloat16* __restrict__ Kl_,
    const __nv_bfloat16* __restrict__ Vh_, const __nv_bfloat16* __restrict__ Vl_,
    const float* __restrict__ Kmask, int bh, int b, int kt, int tid)
{
    const size_t koff = ((size_t)bh*SEQ + kt)*DHEAD;
#pragma unroll
    for (int it = 0; it < 4; it++) {
        const int idx = tid + it*256;
        const int row = idx >> 3;
        const int c   = idx & 7;
        const uint32_t off = SWZ128((uint32_t)(row*128 + c*16));
        const size_t src = koff + (size_t)row*DHEAD + c*8;
        cp_async16(st + 0u*16384u + off, Kh_ + src);
        cp_async16(st + 1u*16384u + off, Kl_ + src);
        cp_async16(st + 2u*16384u + off, Vh_ + src);
        cp_async16(st + 3u*16384u + off, Vl_ + src);
    }
    if (tid < 32)
        cp_async16(st + 65536u + tid*16, Kmask + (size_t)b*SEQ + kt + tid*4);
    CP_COMMIT();
}

__global__ __launch_bounds__(256, 1)
void flash_mma(const __nv_bfloat16* __restrict__ Qh_, const __nv_bfloat16* __restrict__ Ql_,
               const __nv_bfloat16* __restrict__ Kh_, const __nv_bfloat16* __restrict__ Kl_,
               const __nv_bfloat16* __restrict__ Vh_, const __nv_bfloat16* __restrict__ Vl_,
               const float* __restrict__ Qmask, const float* __restrict__ Kmask,
               float* __restrict__ Ctx)
{
    extern __shared__ char smem[];
    const uint32_t sb = smem_u32(smem);
    const int tid  = threadIdx.x;
    const int lane = tid & 31;
    const int wid  = tid >> 5;
    const int q0 = blockIdx.x * 128;
    const int h  = blockIdx.y;
    const int b  = blockIdx.z;
    const int bh = b*NHEADS + h;

    // load Q hi/lo tiles (group 0)
    {
        const size_t qoff = ((size_t)bh*SEQ + q0)*DHEAD;
#pragma unroll
        for (int it = 0; it < 4; it++) {
            const int idx = tid + it*256;
            const int row = idx >> 3;
            const int c   = idx & 7;
            const uint32_t off = SWZ128((uint32_t)(row*128 + c*16));
            const size_t src = qoff + (size_t)row*DHEAD + c*8;
            cp_async16(sb + off, Qh_ + src);
            cp_async16(sb + 16384u + off, Ql_ + src);
        }
        CP_COMMIT();
    }
    load_kv(sb + 32768u,             Kh_, Kl_, Vh_, Vl_, Kmask, bh, b, 0,   tid);
    load_kv(sb + 32768u + AT_STAGE,  Kh_, Kl_, Vh_, Vl_, Kmask, bh, b, 128, tid);

    const int a_row = (wid << 4) + (lane & 15);
    const int a_kh  = (lane >> 4) * 16;
    const int b_rr  = (lane & 7) + ((lane >> 4) << 3);
    const int b_kh  = (lane & 8) ? 16 : 0;

    uint32_t qH[4][4], qL[4][4];
    float O[8][4];
#pragma unroll
    for (int nt = 0; nt < 8; nt++)
#pragma unroll
        for (int j = 0; j < 4; j++) O[nt][j] = 0.0f;
    float m0 = -1e30f, m1 = -1e30f, l0 = 0.f, l1 = 0.f, lm0 = 0.f, lm1 = 0.f;

    for (int i = 0; i < 8; i++) {
        CP_WAIT(1);
        __syncthreads();

        if (i == 0) {
#pragma unroll
            for (int ks = 0; ks < 4; ks++) {
                const uint32_t ao = SWZ128((uint32_t)(a_row*128 + ks*32 + a_kh));
                LDMX4(qH[ks], sb + ao);
                LDMX4(qL[ks], sb + 16384u + ao);
            }
        }

        const uint32_t st = sb + 32768u + (uint32_t)(i & 1)*AT_STAGE;
        const float* Kms = (const float*)(smem + 32768u + (uint32_t)(i & 1)*AT_STAGE + 65536u);

        // ---- S = (QhKh + QhKl + QlKh)^T tile: 16 n-tiles of 8 keys ----
        float S[16][4];
#pragma unroll
        for (int nt = 0; nt < 16; nt++)
#pragma unroll
            for (int j = 0; j < 4; j++) S[nt][j] = 0.0f;

#pragma unroll
        for (int ks = 0; ks < 4; ks++) {
#pragma unroll
            for (int p = 0; p < 8; p++) {
                const uint32_t bo = SWZ128((uint32_t)((p*16 + b_rr)*128 + ks*32 + b_kh));
                uint32_t rh[4], rl[4];
                LDMX4(rh, st + bo);
                LDMX4(rl, st + 16384u + bo);
                uint32_t bh0[2] = {rh[0], rh[1]}, bh1[2] = {rh[2], rh[3]};
                uint32_t bl0[2] = {rl[0], rl[1]}, bl1[2] = {rl[2], rl[3]};
                MMA16816(S[2*p],   qH[ks], bh0);
                MMA16816(S[2*p],   qH[ks], bl0);
                MMA16816(S[2*p],   qL[ks], bh0);
                MMA16816(S[2*p+1], qH[ks], bh1);
                MMA16816(S[2*p+1], qH[ks], bl1);
                MMA16816(S[2*p+1], qL[ks], bh1);
            }
        }

        // ---- online softmax (rows lane/4 and lane/4+8) ----
        float mx0 = -1e30f, mx1 = -1e30f;
#pragma unroll
        for (int nt = 0; nt < 16; nt++) {
            S[nt][0] *= 8.0f; S[nt][1] *= 8.0f; S[nt][2] *= 8.0f; S[nt][3] *= 8.0f;
            mx0 = fmaxf(mx0, fmaxf(S[nt][0], S[nt][1]));
            mx1 = fmaxf(mx1, fmaxf(S[nt][2], S[nt][3]));
        }
        mx0 = fmaxf(mx0, __shfl_xor_sync(0xffffffffu, mx0, 1));
        mx0 = fmaxf(mx0, __shfl_xor_sync(0xffffffffu, mx0, 2));
        mx1 = fmaxf(mx1, __shfl_xor_sync(0xffffffffu, mx1, 1));
        mx1 = fmaxf(mx1, __shfl_xor_sync(0xffffffffu, mx1, 2));

        const float mn0 = fmaxf(m0, mx0), mn1 = fmaxf(m1, mx1);
        const float f0 = __expf(m0 - mn0), f1 = __expf(m1 - mn1);
        float sl0 = 0.f, slm0 = 0.f, sl1 = 0.f, slm1 = 0.f;
#pragma unroll
        for (int nt = 0; nt < 16; nt++) {
            const float kma = Kms[nt*8 + 2*(lane & 3)];
            const float kmb = Kms[nt*8 + 2*(lane & 3) + 1];
            float e0 = __expf(S[nt][0] - mn0); sl0 += e0; float p0 = e0*kma; slm0 += p0; S[nt][0] = p0;
            float e1 = __expf(S[nt][1] - mn0); sl0 += e1; float p1 = e1*kmb; slm0 += p1; S[nt][1] = p1;
            float e2 = __expf(S[nt][2] - mn1); sl1 += e2; float p2 = e2*kma; slm1 += p2; S[nt][2] = p2;
            float e3 = __expf(S[nt][3] - mn1); sl1 += e3; float p3 = e3*kmb; slm1 += p3; S[nt][3] = p3;
        }
#pragma unroll
        for (int o = 1; o <= 2; o <<= 1) {
            sl0  += __shfl_xor_sync(0xffffffffu, sl0,  o);
            slm0 += __shfl_xor_sync(0xffffffffu, slm0, o);
            sl1  += __shfl_xor_sync(0xffffffffu, sl1,  o);
            slm1 += __shfl_xor_sync(0xffffffffu, slm1, o);
        }
        l0 = l0*f0 + sl0;  lm0 = lm0*f0 + slm0;  m0 = mn0;
        l1 = l1*f1 + sl1;  lm1 = lm1*f1 + slm1;  m1 = mn1;
#pragma unroll
        for (int nt = 0; nt < 8; nt++) {
            O[nt][0] *= f0; O[nt][1] *= f0; O[nt][2] *= f1; O[nt][3] *= f1;
        }

        // ---- O += P @ V  (P split to bf16 hi/lo in registers) ----
#pragma unroll
        for (int kc = 0; kc < 8; kc++) {
            uint32_t aPh[4], aPl[4];
            split_pair(S[2*kc][0],   S[2*kc][1],   aPh[0], aPl[0]);
            split_pair(S[2*kc][2],   S[2*kc][3],   aPh[1], aPl[1]);
            split_pair(S[2*kc+1][0], S[2*kc+1][1], aPh[2], aPl[2]);
            split_pair(S[2*kc+1][2], S[2*kc+1][3], aPh[3], aPl[3]);
#pragma unroll
            for (int p = 0; p < 4; p++) {
                const uint32_t vo = SWZ128((uint32_t)((kc*16 + (lane & 15))*128 + p*32 + (lane >> 4)*16));
                uint32_t vh[4], vl[4];
                LDMX4T(vh, st + 2u*16384u + vo);
                LDMX4T(vl, st + 3u*16384u + vo);
                uint32_t vh0[2] = {vh[0], vh[1]}, vh1[2] = {vh[2], vh[3]};
                uint32_t vl0[2] = {vl[0], vl[1]}, vl1[2] = {vl[2], vl[3]};
                MMA16816(O[2*p],   aPh, vh0);
                MMA16816(O[2*p],   aPh, vl0);
                MMA16816(O[2*p],   aPl, vh0);
                MMA16816(O[2*p+1], aPh, vh1);
                MMA16816(O[2*p+1], aPh, vl1);
                MMA16816(O[2*p+1], aPl, vh1);
            }
        }

        __syncthreads();
        if (i + 2 < 8)
            load_kv(st, Kh_, Kl_, Vh_, Vl_, Kmask, bh, b, (i + 2)*128, tid);
    }

    // ---- epilogue: out = Qm * O / (lm + l*S*ZERO) ----
    const int r0 = q0 + (wid << 4) + (lane >> 2);
    const float qm0 = Qmask[(size_t)b*SEQ + r0];
    const float qm1 = Qmask[(size_t)b*SEQ + r0 + 8];
    const float inv0 = qm0 / (lm0 + l0*SZTERM);
    const float inv1 = qm1 / (lm1 + l1*SZTERM);
    const size_t base0 = ((size_t)b*SEQ + r0)*HIDDEN + h*DHEAD + 2*(lane & 3);
    const size_t base1 = base0 + (size_t)8*HIDDEN;
#pragma unroll
    for (int nt = 0; nt < 8; nt++) {
        *(float2*)&Ctx[base0 + nt*8] = make_float2(O[nt][0]*inv0, O[nt][1]*inv0);
        *(float2*)&Ctx[base1 + nt*8] = make_float2(O[nt][2]*inv1, O[nt][3]*inv1);
    }
}

// ---------------- launch ----------------
extern "C" void kernel_launch(void* const* d_in, const int* in_sizes, int n_in,
                              void* d_out, int out_size)
{
    const float* Q   = (const float*)d_in[0];
    const float* K   = (const float*)d_in[1];
    const float* V   = (const float*)d_in[2];
    const float* Qm  = (const float*)d_in[3];
    const float* Km  = (const float*)d_in[4];
    const float* Wq  = (const float*)d_in[5];
    const float* bq  = (const float*)d_in[6];
    const float* Wk  = (const float*)d_in[7];
    const float* bk  = (const float*)d_in[8];
    const float* Wv  = (const float*)d_in[9];
    const float* bv  = (const float*)d_in[10];
    const float* Wo  = (const float*)d_in[11];
    const float* bo  = (const float*)d_in[12];
    float* out = (float*)d_out;

    float *gctx;
    __nv_bfloat16 *ah, *al, *wh, *wl, *qh, *ql, *kh, *kl, *vh, *vl;
    cudaGetSymbolAddress((void**)&gctx, g_ctx);
    cudaGetSymbolAddress((void**)&ah,   g_ah);
    cudaGetSymbolAddress((void**)&al,   g_al);
    cudaGetSymbolAddress((void**)&wh,   g_wh);
    cudaGetSymbolAddress((void**)&wl,   g_wl);
    cudaGetSymbolAddress((void**)&qh,   g_qh);
    cudaGetSymbolAddress((void**)&ql,   g_ql);
    cudaGetSymbolAddress((void**)&kh,   g_kh);
    cudaGetSymbolAddress((void**)&kl,   g_kl);
    cudaGetSymbolAddress((void**)&vh,   g_vh);
    cudaGetSymbolAddress((void**)&vl,   g_vl);

    cudaFuncSetAttribute(tcgemm, cudaFuncAttributeMaxDynamicSharedMemorySize, (int)TC_SMEM);
    cudaFuncSetAttribute(flash_mma, cudaFuncAttributeMaxDynamicSharedMemorySize, (int)AT_SMEM);

    const int nA4 = MTOT*HIDDEN/4;
    const int nW4 = HIDDEN*HIDDEN/4;
    dim3 ggrd(HIDDEN/128, MTOT/128);

    // Q projection -> bf16 split [b][h][s][d]
    split_bf16<<<nA4/256, 256>>>(Q, ah, al, nA4);
    split_bf16<<<nW4/256, 256>>>(Wq, wh, wl, nW4);
    tcgemm<<<ggrd, 256, TC_SMEM>>>(ah, al, wh, wl, bq, nullptr, qh, ql, 1);
    // K projection
    split_bf16<<<nA4/256, 256>>>(K, ah, al, nA4);
    split_bf16<<<nW4/256, 256>>>(Wk, wh, wl, nW4);
    tcgemm<<<ggrd, 256, TC_SMEM>>>(ah, al, wh, wl, bk, nullptr, kh, kl, 1);
    // V projection
    split_bf16<<<nA4/256, 256>>>(V, ah, al, nA4);
    split_bf16<<<nW4/256, 256>>>(Wv, wh, wl, nW4);
    tcgemm<<<ggrd, 256, TC_SMEM>>>(ah, al, wh, wl, bv, nullptr, vh, vl, 1);

    // attention (tensor cores)
    dim3 fgrd(SEQ/128, NHEADS, NB);
    flash_mma<<<fgrd, 256, AT_SMEM>>>(qh, ql, kh, kl, vh, vl, Qm, Km, gctx);

    // output projection (fp32 out)
    split_bf16<<<nA4/256, 256>>>(gctx, ah, al, nA4);
    split_bf16<<<nW4/256, 256>>>(Wo, wh, wl, nW4);
    tcgemm<<<ggrd, 256, TC_SMEM>>>(ah, al, wh, wl, bo, out, nullptr, nullptr, 0);

    (void)in_sizes; (void)n_in; (void)out_size;
}

// round 14
// speedup vs baseline: 1.7153x; 1.0005x over previous
#include <cuda_runtime.h>
#include <cuda_bf16.h>
#include <cstdint>

#define NB      8
#define SEQ     1024
#define HIDDEN  1024
#define NHEADS  16
#define DHEAD   64
#define MTOT    (NB*SEQ)        // 8192
#define SZTERM  1.024e-5f       // S * ZERO = 1024 * 1e-8

// ---------------- scratch (no allocations allowed) ----------------
__device__ float g_ctx[NB*SEQ*HIDDEN];             // [b][s][h*64+d]
__device__ __nv_bfloat16 g_ah[MTOT*HIDDEN];        // GEMM A hi
__device__ __nv_bfloat16 g_al[MTOT*HIDDEN];        // GEMM A lo
__device__ __nv_bfloat16 g_wh[HIDDEN*HIDDEN];      // W hi
__device__ __nv_bfloat16 g_wl[HIDDEN*HIDDEN];      // W lo
__device__ __nv_bfloat16 g_qh[NB*NHEADS*SEQ*DHEAD];  // [b][h][s][d] splits
__device__ __nv_bfloat16 g_ql[NB*NHEADS*SEQ*DHEAD];
__device__ __nv_bfloat16 g_kh[NB*NHEADS*SEQ*DHEAD];
__device__ __nv_bfloat16 g_kl[NB*NHEADS*SEQ*DHEAD];
__device__ __nv_bfloat16 g_vh[NB*NHEADS*SEQ*DHEAD];
__device__ __nv_bfloat16 g_vl[NB*NHEADS*SEQ*DHEAD];

// ================= helpers =================
__device__ __forceinline__ uint32_t smem_u32(const void* p) {
    uint32_t a;
    asm("{ .reg .u64 t; cvta.to.shared.u64 t, %1; cvt.u32.u64 %0, t; }" : "=r"(a) : "l"(p));
    return a;
}
__device__ __forceinline__ void cp_async16(uint32_t dst, const void* src) {
    asm volatile("cp.async.cg.shared.global [%0], [%1], 16;" :: "r"(dst), "l"(src) : "memory");
}
#define CP_COMMIT()  asm volatile("cp.async.commit_group;" ::: "memory")
#define CP_WAIT(n)   asm volatile("cp.async.wait_group %0;" :: "n"(n) : "memory")

#define SWZ128(o) ((o) ^ (((o) >> 3) & 0x70))

#define LDMX4(r, a) \
    asm volatile("ldmatrix.sync.aligned.m8n8.x4.shared.b16 {%0,%1,%2,%3}, [%4];" \
        : "=r"((r)[0]), "=r"((r)[1]), "=r"((r)[2]), "=r"((r)[3]) : "r"(a))

#define LDMX4T(r, a) \
    asm volatile("ldmatrix.sync.aligned.m8n8.x4.trans.shared.b16 {%0,%1,%2,%3}, [%4];" \
        : "=r"((r)[0]), "=r"((r)[1]), "=r"((r)[2]), "=r"((r)[3]) : "r"(a))

#define MMA16816(c, a, b) \
    asm volatile("mma.sync.aligned.m16n8k16.row.col.f32.bf16.bf16.f32 " \
        "{%0,%1,%2,%3}, {%4,%5,%6,%7}, {%8,%9}, {%0,%1,%2,%3};" \
        : "+f"((c)[0]), "+f"((c)[1]), "+f"((c)[2]), "+f"((c)[3]) \
        : "r"((a)[0]), "r"((a)[1]), "r"((a)[2]), "r"((a)[3]), "r"((b)[0]), "r"((b)[1]))

__device__ __forceinline__ uint32_t pack_bf2(__nv_bfloat16 x, __nv_bfloat16 y) {
    __nv_bfloat162 t = __halves2bfloat162(x, y);
    return *(uint32_t*)&t;
}
__device__ __forceinline__ void split_pair(float x, float y, uint32_t& hi, uint32_t& lo) {
    __nv_bfloat16 hx = __float2bfloat16_rn(x);
    __nv_bfloat16 hy = __float2bfloat16_rn(y);
    hi = pack_bf2(hx, hy);
    lo = pack_bf2(__float2bfloat16_rn(x - __bfloat162float(hx)),
                  __float2bfloat16_rn(y - __bfloat162float(hy)));
}

// ================= fp32 -> bf16 hi/lo split =================
__global__ __launch_bounds__(256)
void split_bf16(const float* __restrict__ x, __nv_bfloat16* __restrict__ hi,
                __nv_bfloat16* __restrict__ lo, int n4)
{
    int i = blockIdx.x * blockDim.x + threadIdx.x;
    if (i >= n4) return;
    float4 v = ((const float4*)x)[i];
    float f[4] = {v.x, v.y, v.z, v.w};
    __nv_bfloat16 h[4], l[4];
#pragma unroll
    for (int j = 0; j < 4; j++) {
        h[j] = __float2bfloat16_rn(f[j]);
        l[j] = __float2bfloat16_rn(f[j] - __bfloat162float(h[j]));
    }
    __nv_bfloat162* H = (__nv_bfloat162*)hi;
    __nv_bfloat162* L = (__nv_bfloat162*)lo;
    H[2*i]   = __halves2bfloat162(h[0], h[1]);
    H[2*i+1] = __halves2bfloat162(h[2], h[3]);
    L[2*i]   = __halves2bfloat162(l[0], l[1]);
    L[2*i+1] = __halves2bfloat162(l[2], l[3]);
}

// ================= mma.sync GEMM: C = A[M,K] @ W[N,K]^T + bias =================
// mode 0: fp32 output [m][n];  mode 1: bf16 hi/lo split output in [b][h][s][d]
#define TILE_BYTES 16384u
#define STAGE_BYTES (4u*TILE_BYTES)
#define TC_SMEM (3u*STAGE_BYTES)         // 196608

__device__ __forceinline__ void load_chunk(
    const __nv_bfloat16* __restrict__ Ah, const __nv_bfloat16* __restrict__ Al,
    const __nv_bfloat16* __restrict__ Bh, const __nv_bfloat16* __restrict__ Bl,
    int m0, int n0, int kc, uint32_t buf, int tid)
{
#pragma unroll
    for (int it = 0; it < 4; it++) {
        const int idx = tid + it*256;
        const int row = idx >> 3;
        const int c   = idx & 7;
        const uint32_t off = SWZ128((uint32_t)(row*128 + c*16));
        const size_t arow = (size_t)(m0 + row) * HIDDEN + kc*64 + c*8;
        const size_t brow = (size_t)(n0 + row) * HIDDEN + kc*64 + c*8;
        cp_async16(buf + 0*TILE_BYTES + off, Ah + arow);
        cp_async16(buf + 1*TILE_BYTES + off, Al + arow);
        cp_async16(buf + 2*TILE_BYTES + off, Bh + brow);
        cp_async16(buf + 3*TILE_BYTES + off, Bl + brow);
    }
    CP_COMMIT();
}

__global__ __launch_bounds__(256, 1)
void tcgemm(const __nv_bfloat16* __restrict__ Ah, const __nv_bfloat16* __restrict__ Al,
            const __nv_bfloat16* __restrict__ Bh, const __nv_bfloat16* __restrict__ Bl,
            const float* __restrict__ bias, float* __restrict__ Cf,
            __nv_bfloat16* __restrict__ Ch, __nv_bfloat16* __restrict__ Cl, int mode)
{
    extern __shared__ char smem[];
    const uint32_t sb = smem_u32(smem);
    const int tid  = threadIdx.x;
    const int lane = tid & 31;
    const int wid  = tid >> 5;
    const int m0 = blockIdx.y * 128;
    const int n0 = blockIdx.x * 128;
    const int wm = (wid & 1) * 64;
    const int wn = (wid >> 1) * 32;

    const int a_row = wm + (lane & 15);
    const int a_kh  = (lane >> 4) * 16;
    const int b_rr  = (lane & 7) + ((lane >> 4) << 3);
    const int b_kh  = (lane & 8) ? 16 : 0;

    float acc[4][4][4];
#pragma unroll
    for (int mt = 0; mt < 4; mt++)
#pragma unroll
        for (int nt = 0; nt < 4; nt++)
#pragma unroll
            for (int j = 0; j < 4; j++) acc[mt][nt][j] = 0.0f;

#pragma unroll
    for (int s = 0; s < 3; s++)
        load_chunk(Ah, Al, Bh, Bl, m0, n0, s, sb + s*STAGE_BYTES, tid);

    for (int i = 0; i < 16; i++) {
        if (i < 14)       CP_WAIT(2);
        else if (i == 14) CP_WAIT(1);
        else              CP_WAIT(0);
        __syncthreads();

        const uint32_t buf = sb + (uint32_t)(i % 3) * STAGE_BYTES;
        const uint32_t bAh = buf;
        const uint32_t bAl = buf + 1*TILE_BYTES;
        const uint32_t bBh = buf + 2*TILE_BYTES;
        const uint32_t bBl = buf + 3*TILE_BYTES;

#pragma unroll
        for (int ks = 0; ks < 4; ks++) {
            const int kb = ks * 32;
            uint32_t aH[4][4], aL[4][4], bH[4][2], bL[4][2];
#pragma unroll
            for (int mt = 0; mt < 4; mt++) {
                const uint32_t ao = SWZ128((uint32_t)((a_row + mt*16)*128 + kb + a_kh));
                LDMX4(aH[mt], bAh + ao);
                LDMX4(aL[mt], bAl + ao);
            }
#pragma unroll
            for (int p = 0; p < 2; p++) {
                const uint32_t bo = SWZ128((uint32_t)((wn + p*16 + b_rr)*128 + kb + b_kh));
                uint32_t rh[4], rl[4];
                LDMX4(rh, bBh + bo);
                LDMX4(rl, bBl + bo);
                bH[2*p][0] = rh[0]; bH[2*p][1] = rh[1];
                bH[2*p+1][0] = rh[2]; bH[2*p+1][1] = rh[3];
                bL[2*p][0] = rl[0]; bL[2*p][1] = rl[1];
                bL[2*p+1][0] = rl[2]; bL[2*p+1][1] = rl[3];
            }
#pragma unroll
            for (int mt = 0; mt < 4; mt++)
#pragma unroll
                for (int nt = 0; nt < 4; nt++) {
                    MMA16816(acc[mt][nt], aH[mt], bH[nt]);
                    MMA16816(acc[mt][nt], aH[mt], bL[nt]);
                    MMA16816(acc[mt][nt], aL[mt], bH[nt]);
                }
        }
        __syncthreads();
        if (i + 3 < 16)
            load_chunk(Ah, Al, Bh, Bl, m0, n0, i + 3, buf, tid);
    }

#pragma unroll
    for (int mt = 0; mt < 4; mt++) {
        const int r0 = wm + mt*16 + (lane >> 2);
#pragma unroll
        for (int half = 0; half < 2; half++) {
            const int m  = m0 + r0 + half*8;
            const int bb = m >> 10;
            const int ss = m & 1023;
#pragma unroll
            for (int nt = 0; nt < 4; nt++) {
                const int n = n0 + wn + nt*8 + 2*(lane & 3);
                float v0 = acc[mt][nt][half*2+0] + bias[n];
                float v1 = acc[mt][nt][half*2+1] + bias[n+1];
                if (mode == 1) {
                    const int hh = n >> 6;
                    const int d  = n & 63;
                    const size_t idx = (((size_t)(bb*NHEADS + hh))*SEQ + ss)*DHEAD + d;
                    __nv_bfloat16 h0 = __float2bfloat16_rn(v0);
                    __nv_bfloat16 h1 = __float2bfloat16_rn(v1);
                    *(__nv_bfloat162*)(Ch + idx) = __halves2bfloat162(h0, h1);
                    *(__nv_bfloat162*)(Cl + idx) = __halves2bfloat162(
                        __float2bfloat16_rn(v0 - __bfloat162float(h0)),
                        __float2bfloat16_rn(v1 - __bfloat162float(h1)));
                } else {
                    *(float2*)(Cf + (size_t)m * HIDDEN + n) = make_float2(v0, v1);
                }
            }
        }
    }
}

// ================= tensor-core flash attention =================
// CTA: 128 q rows x one (b,h). 8 warps, warp = 16 q rows x 128 keys.
// smem: Qh/Ql tiles (32KB) + 2 stages of {Kh,Kl,Vh,Vl,Kms} (66048 B each)
#define AT_STAGE 66048u
#define AT_SMEM  (32768u + 2u*AT_STAGE)   // 164864

__device__ __forceinline__ void load_kv(
    uint32_t st, const __nv_bfloat16* __restrict__ Kh_, const __nv_bfloat16* __restrict__ Kl_,
    const __nv_bfloat16* __restrict__ Vh_, const __nv_bfloat16* __restrict__ Vl_,
    const float* __restrict__ Kmask, int bh, int b, int kt, int tid)
{
    const size_t koff = ((size_t)bh*SEQ + kt)*DHEAD;
#pragma unroll
    for (int it = 0; it < 4; it++) {
        const int idx = tid + it*256;
        const int row = idx >> 3;
        const int c   = idx & 7;
        const uint32_t off = SWZ128((uint32_t)(row*128 + c*16));
        const size_t src = koff + (size_t)row*DHEAD + c*8;
        cp_async16(st + 0u*16384u + off, Kh_ + src);
        cp_async16(st + 1u*16384u + off, Kl_ + src);
        cp_async16(st + 2u*16384u + off, Vh_ + src);
        cp_async16(st + 3u*16384u + off, Vl_ + src);
    }
    if (tid < 32)
        cp_async16(st + 65536u + tid*16, Kmask + (size_t)b*SEQ + kt + tid*4);
    CP_COMMIT();
}

__global__ __launch_bounds__(256, 1)
void flash_mma(const __nv_bfloat16* __restrict__ Qh_, const __nv_bfloat16* __restrict__ Ql_,
               const __nv_bfloat16* __restrict__ Kh_, const __nv_bfloat16* __restrict__ Kl_,
               const __nv_bfloat16* __restrict__ Vh_, const __nv_bfloat16* __restrict__ Vl_,
               const float* __restrict__ Qmask, const float* __restrict__ Kmask,
               float* __restrict__ Ctx)
{
    extern __shared__ char smem[];
    const uint32_t sb = smem_u32(smem);
    const int tid  = threadIdx.x;
    const int lane = tid & 31;
    const int wid  = tid >> 5;
    const int q0 = blockIdx.x * 128;
    const int h  = blockIdx.y;
    const int b  = blockIdx.z;
    const int bh = b*NHEADS + h;

    // load Q hi/lo tiles (group 0)
    {
        const size_t qoff = ((size_t)bh*SEQ + q0)*DHEAD;
#pragma unroll
        for (int it = 0; it < 4; it++) {
            const int idx = tid + it*256;
            const int row = idx >> 3;
            const int c   = idx & 7;
            const uint32_t off = SWZ128((uint32_t)(row*128 + c*16));
            const size_t src = qoff + (size_t)row*DHEAD + c*8;
            cp_async16(sb + off, Qh_ + src);
            cp_async16(sb + 16384u + off, Ql_ + src);
        }
        CP_COMMIT();
    }
    load_kv(sb + 32768u,             Kh_, Kl_, Vh_, Vl_, Kmask, bh, b, 0,   tid);
    load_kv(sb + 32768u + AT_STAGE,  Kh_, Kl_, Vh_, Vl_, Kmask, bh, b, 128, tid);

    const int a_row = (wid << 4) + (lane & 15);
    const int a_kh  = (lane >> 4) * 16;
    const int b_rr  = (lane & 7) + ((lane >> 4) << 3);
    const int b_kh  = (lane & 8) ? 16 : 0;

    uint32_t qH[4][4], qL[4][4];
    float O[8][4];
#pragma unroll
    for (int nt = 0; nt < 8; nt++)
#pragma unroll
        for (int j = 0; j < 4; j++) O[nt][j] = 0.0f;
    float m0 = -1e30f, m1 = -1e30f, l0 = 0.f, l1 = 0.f, lm0 = 0.f, lm1 = 0.f;

    for (int i = 0; i < 8; i++) {
        CP_WAIT(1);
        __syncthreads();

        if (i == 0) {
#pragma unroll
            for (int ks = 0; ks < 4; ks++) {
                const uint32_t ao = SWZ128((uint32_t)(a_row*128 + ks*32 + a_kh));
                LDMX4(qH[ks], sb + ao);
                LDMX4(qL[ks], sb + 16384u + ao);
            }
        }

        const uint32_t st = sb + 32768u + (uint32_t)(i & 1)*AT_STAGE;
        const float* Kms = (const float*)(smem + 32768u + (uint32_t)(i & 1)*AT_STAGE + 65536u);

        // ---- S = (QhKh + QhKl + QlKh)^T tile: 16 n-tiles of 8 keys ----
        float S[16][4];
#pragma unroll
        for (int nt = 0; nt < 16; nt++)
#pragma unroll
            for (int j = 0; j < 4; j++) S[nt][j] = 0.0f;

#pragma unroll
        for (int ks = 0; ks < 4; ks++) {
#pragma unroll
            for (int p = 0; p < 8; p++) {
                const uint32_t bo = SWZ128((uint32_t)((p*16 + b_rr)*128 + ks*32 + b_kh));
                uint32_t rh[4], rl[4];
                LDMX4(rh, st + bo);
                LDMX4(rl, st + 16384u + bo);
                uint32_t bh0[2] = {rh[0], rh[1]}, bh1[2] = {rh[2], rh[3]};
                uint32_t bl0[2] = {rl[0], rl[1]}, bl1[2] = {rl[2], rl[3]};
                MMA16816(S[2*p],   qH[ks], bh0);
                MMA16816(S[2*p],   qH[ks], bl0);
                MMA16816(S[2*p],   qL[ks], bh0);
                MMA16816(S[2*p+1], qH[ks], bh1);
                MMA16816(S[2*p+1], qH[ks], bl1);
                MMA16816(S[2*p+1], qL[ks], bh1);
            }
        }

        // ---- online softmax (rows lane/4 and lane/4+8) ----
        float mx0 = -1e30f, mx1 = -1e30f;
#pragma unroll
        for (int nt = 0; nt < 16; nt++) {
            S[nt][0] *= 8.0f; S[nt][1] *= 8.0f; S[nt][2] *= 8.0f; S[nt][3] *= 8.0f;
            mx0 = fmaxf(mx0, fmaxf(S[nt][0], S[nt][1]));
            mx1 = fmaxf(mx1, fmaxf(S[nt][2], S[nt][3]));
        }
        mx0 = fmaxf(mx0, __shfl_xor_sync(0xffffffffu, mx0, 1));
        mx0 = fmaxf(mx0, __shfl_xor_sync(0xffffffffu, mx0, 2));
        mx1 = fmaxf(mx1, __shfl_xor_sync(0xffffffffu, mx1, 1));
        mx1 = fmaxf(mx1, __shfl_xor_sync(0xffffffffu, mx1, 2));

        const float mn0 = fmaxf(m0, mx0), mn1 = fmaxf(m1, mx1);
        const float f0 = __expf(m0 - mn0), f1 = __expf(m1 - mn1);
        float sl0 = 0.f, slm0 = 0.f, sl1 = 0.f, slm1 = 0.f;
#pragma unroll
        for (int nt = 0; nt < 16; nt++) {
            const float kma = Kms[nt*8 + 2*(lane & 3)];
            const float kmb = Kms[nt*8 + 2*(lane & 3) + 1];
            float e0 = __expf(S[nt][0] - mn0); sl0 += e0; float p0 = e0*kma; slm0 += p0; S[nt][0] = p0;
            float e1 = __expf(S[nt][1] - mn0); sl0 += e1; float p1 = e1*kmb; slm0 += p1; S[nt][1] = p1;
            float e2 = __expf(S[nt][2] - mn1); sl1 += e2; float p2 = e2*kma; slm1 += p2; S[nt][2] = p2;
            float e3 = __expf(S[nt][3] - mn1); sl1 += e3; float p3 = e3*kmb; slm1 += p3; S[nt][3] = p3;
        }
#pragma unroll
        for (int o = 1; o <= 2; o <<= 1) {
            sl0  += __shfl_xor_sync(0xffffffffu, sl0,  o);
            slm0 += __shfl_xor_sync(0xffffffffu, slm0, o);
            sl1  += __shfl_xor_sync(0xffffffffu, sl1,  o);
            slm1 += __shfl_xor_sync(0xffffffffu, slm1, o);
        }
        l0 = l0*f0 + sl0;  lm0 = lm0*f0 + slm0;  m0 = mn0;
        l1 = l1*f1 + sl1;  lm1 = lm1*f1 + slm1;  m1 = mn1;
#pragma unroll
        for (int nt = 0; nt < 8; nt++) {
            O[nt][0] *= f0; O[nt][1] *= f0; O[nt][2] *= f1; O[nt][3] *= f1;
        }

        // ---- O += P @ V  (P split to bf16 hi/lo in registers) ----
#pragma unroll
        for (int kc = 0; kc < 8; kc++) {
            uint32_t aPh[4], aPl[4];
            split_pair(S[2*kc][0],   S[2*kc][1],   aPh[0], aPl[0]);
            split_pair(S[2*kc][2],   S[2*kc][3],   aPh[1], aPl[1]);
            split_pair(S[2*kc+1][0], S[2*kc+1][1], aPh[2], aPl[2]);
            split_pair(S[2*kc+1][2], S[2*kc+1][3], aPh[3], aPl[3]);
#pragma unroll
            for (int p = 0; p < 4; p++) {
                const uint32_t vo = SWZ128((uint32_t)((kc*16 + (lane & 15))*128 + p*32 + (lane >> 4)*16));
                uint32_t vh[4], vl[4];
                LDMX4T(vh, st + 2u*16384u + vo);
                LDMX4T(vl, st + 3u*16384u + vo);
                uint32_t vh0[2] = {vh[0], vh[1]}, vh1[2] = {vh[2], vh[3]};
                uint32_t vl0[2] = {vl[0], vl[1]}, vl1[2] = {vl[2], vl[3]};
                MMA16816(O[2*p],   aPh, vh0);
                MMA16816(O[2*p],   aPh, vl0);
                MMA16816(O[2*p],   aPl, vh0);
                MMA16816(O[2*p+1], aPh, vh1);
                MMA16816(O[2*p+1], aPh, vl1);
                MMA16816(O[2*p+1], aPl, vh1);
            }
        }

        __syncthreads();
        if (i + 2 < 8)
            load_kv(st, Kh_, Kl_, Vh_, Vl_, Kmask, bh, b, (i + 2)*128, tid);
    }

    // ---- epilogue: out = Qm * O / (lm + l*S*ZERO) ----
    const int r0 = q0 + (wid << 4) + (lane >> 2);
    const float qm0 = Qmask[(size_t)b*SEQ + r0];
    const float qm1 = Qmask[(size_t)b*SEQ + r0 + 8];
    const float inv0 = qm0 / (lm0 + l0*SZTERM);
    const float inv1 = qm1 / (lm1 + l1*SZTERM);
    const size_t base0 = ((size_t)b*SEQ + r0)*HIDDEN + h*DHEAD + 2*(lane & 3);
    const size_t base1 = base0 + (size_t)8*HIDDEN;
#pragma unroll
    for (int nt = 0; nt < 8; nt++) {
        *(float2*)&Ctx[base0 + nt*8] = make_float2(O[nt][0]*inv0, O[nt][1]*inv0);
        *(float2*)&Ctx[base1 + nt*8] = make_float2(O[nt][2]*inv1, O[nt][3]*inv1);
    }
}

// ---------------- launch ----------------
extern "C" void kernel_launch(void* const* d_in, const int* in_sizes, int n_in,
                              void* d_out, int out_size)
{
    const float* Q   = (const float*)d_in[0];
    const float* K   = (const float*)d_in[1];
    const float* V   = (const float*)d_in[2];
    const float* Qm  = (const float*)d_in[3];
    const float* Km  = (const float*)d_in[4];
    const float* Wq  = (const float*)d_in[5];
    const float* bq  = (const float*)d_in[6];
    const float* Wk  = (const float*)d_in[7];
    const float* bk  = (const float*)d_in[8];
    const float* Wv  = (const float*)d_in[9];
    const float* bv  = (const float*)d_in[10];
    const float* Wo  = (const float*)d_in[11];
    const float* bo  = (const float*)d_in[12];
    float* out = (float*)d_out;

    float *gctx;
    __nv_bfloat16 *ah, *al, *wh, *wl, *qh, *ql, *kh, *kl, *vh, *vl;
    cudaGetSymbolAddress((void**)&gctx, g_ctx);
    cudaGetSymbolAddress((void**)&ah,   g_ah);
    cudaGetSymbolAddress((void**)&al,   g_al);
    cudaGetSymbolAddress((void**)&wh,   g_wh);
    cudaGetSymbolAddress((void**)&wl,   g_wl);
    cudaGetSymbolAddress((void**)&qh,   g_qh);
    cudaGetSymbolAddress((void**)&ql,   g_ql);
    cudaGetSymbolAddress((void**)&kh,   g_kh);
    cudaGetSymbolAddress((void**)&kl,   g_kl);
    cudaGetSymbolAddress((void**)&vh,   g_vh);
    cudaGetSymbolAddress((void**)&vl,   g_vl);

    cudaFuncSetAttribute(tcgemm, cudaFuncAttributeMaxDynamicSharedMemorySize, (int)TC_SMEM);
    cudaFuncSetAttribute(flash_mma, cudaFuncAttributeMaxDynamicSharedMemorySize, (int)AT_SMEM);

    const int nA4 = MTOT*HIDDEN/4;
    const int nW4 = HIDDEN*HIDDEN/4;
    dim3 ggrd(HIDDEN/128, MTOT/128);

    // Q projection -> bf16 split [b][h][s][d]
    split_bf16<<<nA4/256, 256>>>(Q, ah, al, nA4);
    split_bf16<<<nW4/256, 256>>>(Wq, wh, wl, nW4);
    tcgemm<<<ggrd, 256, TC_SMEM>>>(ah, al, wh, wl, bq, nullptr, qh, ql, 1);
    // K projection
    split_bf16<<<nA4/256, 256>>>(K, ah, al, nA4);
    split_bf16<<<nW4/256, 256>>>(Wk, wh, wl, nW4);
    tcgemm<<<ggrd, 256, TC_SMEM>>>(ah, al, wh, wl, bk, nullptr, kh, kl, 1);
    // V projection
    split_bf16<<<nA4/256, 256>>>(V, ah, al, nA4);
    split_bf16<<<nW4/256, 256>>>(Wv, wh, wl, nW4);
    tcgemm<<<ggrd, 256, TC_SMEM>>>(ah, al, wh, wl, bv, nullptr, vh, vl, 1);

    // attention (tensor cores)
    dim3 fgrd(SEQ/128, NHEADS, NB);
    flash_mma<<<fgrd, 256, AT_SMEM>>>(qh, ql, kh, kl, vh, vl, Qm, Km, gctx);

    // output projection (fp32 out)
    split_bf16<<<nA4/256, 256>>>(gctx, ah, al, nA4);
    split_bf16<<<nW4/256, 256>>>(Wo, wh, wl, nW4);
    tcgemm<<<ggrd, 256, TC_SMEM>>>(ah, al, wh, wl, bo, out, nullptr, nullptr, 0);

    (void)in_sizes; (void)n_in; (void)out_size;
}